// round 1
// baseline (speedup 1.0000x reference)
#include <cuda_runtime.h>
#include <cstdint>
#include <cstddef>

// Problem constants
#define BB    8192
#define NN    17
#define CIN   256
#define COUT  256
#define DT    64          // d-tile width per block
#define NTILE 4           // COUT / DT
#define BGRP  148         // b-group count (one per SM)

// Precomputed small tensors
__device__ float d_offA[NN * NN];      // symmetrized A with zeroed diagonal
__device__ float d_Cdiag[NN * COUT];   // A[i,i] * M[i,d]

// ---------------------------------------------------------------------------
// Prep kernel: symmetrize A = adj + adj2, split diag/offdiag, fold diag into M
// ---------------------------------------------------------------------------
__global__ void prep_kernel(const float* __restrict__ M,
                            const float* __restrict__ adj,
                            const float* __restrict__ adj2) {
    __shared__ float Asym[NN * NN];
    int t = threadIdx.x;
    for (int idx = t; idx < NN * NN; idx += blockDim.x) {
        int i = idx / NN, j = idx % NN;
        float a = adj[i * NN + j] + adj2[i * NN + j];
        float b = adj[j * NN + i] + adj2[j * NN + i];
        Asym[idx] = 0.5f * (a + b);
    }
    __syncthreads();
    for (int idx = t; idx < NN * NN; idx += blockDim.x) {
        int i = idx / NN, j = idx % NN;
        d_offA[idx] = (i == j) ? 0.0f : Asym[idx];
    }
    for (int idx = t; idx < NN * COUT; idx += blockDim.x) {
        int i = idx >> 8;  // / COUT
        d_Cdiag[idx] = Asym[i * NN + i] * M[idx];
    }
}

// ---------------------------------------------------------------------------
// Main fused kernel: dual GEMM (x@W0, x@W1) + modulated graph aggregation
// Block: 256 threads. blockIdx.x = d-tile (0..3), blockIdx.y = b-group.
// Thread t: dloc = t & 63, grp = t >> 6; grp g owns rows n = g, g+4, g+8, ...
// ---------------------------------------------------------------------------
__global__ void __launch_bounds__(256, 1)
mgc_kernel(const float* __restrict__ x,
           const float* __restrict__ W,
           const float* __restrict__ M,
           const float* __restrict__ bias,
           float* __restrict__ out) {
    extern __shared__ float smem[];
    float* Ws0 = smem;                       // [CIN][DT]  16384
    float* Ws1 = Ws0 + CIN * DT;             // [CIN][DT]  16384
    float* xs  = Ws1 + CIN * DT;             // [NN][CIN]   4352
    float* Msh = xs + NN * CIN;              // [NN][DT]    1088
    float* Cds = Msh + NN * DT;              // [NN][DT]    1088
    float* g1s = Cds + NN * DT;              // [NN][DT]    1088
    float* bss = g1s + NN * DT;              // [DT]          64
    float* oAs = bss + DT;                   // [NN][NN]     289

    const int t    = threadIdx.x;
    const int dloc = t & (DT - 1);
    const int grp  = t >> 6;
    const int d0   = blockIdx.x * DT;

    // One-time per-block loads (W d-slice, M/Cdiag/bias tiles, offA)
    for (int idx = t; idx < CIN * DT; idx += 256) {
        int k = idx >> 6, dl = idx & (DT - 1);
        Ws0[idx] = W[k * COUT + d0 + dl];
        Ws1[idx] = W[CIN * COUT + k * COUT + d0 + dl];
    }
    for (int idx = t; idx < NN * DT; idx += 256) {
        int n = idx >> 6, dl = idx & (DT - 1);
        Msh[idx] = M[n * COUT + d0 + dl];
        Cds[idx] = d_Cdiag[n * COUT + d0 + dl];
    }
    if (t < DT) bss[t] = bias[d0 + t];
    for (int idx = t; idx < NN * NN; idx += 256) oAs[idx] = d_offA[idx];
    __syncthreads();

    // Row list for this thread group (grp 0 gets 5 rows incl. n=16)
    int nrow[5];
    const int ncnt = (grp == 0) ? 5 : 4;
#pragma unroll
    for (int q = 0; q < 5; q++) nrow[q] = grp + 4 * q;

    const float4* __restrict__ xg4 = (const float4*)x;
    float4* xs4 = (float4*)xs;

    for (int b = blockIdx.y; b < BB; b += gridDim.y) {
        // Load x[b] (17x256 f32 = 1088 float4) into shared
        for (int idx = t; idx < NN * CIN / 4; idx += 256)
            xs4[idx] = xg4[(size_t)b * (NN * CIN / 4) + idx];
        __syncthreads();

        float acc0[5] = {0.f, 0.f, 0.f, 0.f, 0.f};
        float acc1[5] = {0.f, 0.f, 0.f, 0.f, 0.f};

#pragma unroll 2
        for (int k4 = 0; k4 < CIN / 4; k4++) {
            const int k = k4 * 4;
            const float w00 = Ws0[(k + 0) * DT + dloc];
            const float w01 = Ws0[(k + 1) * DT + dloc];
            const float w02 = Ws0[(k + 2) * DT + dloc];
            const float w03 = Ws0[(k + 3) * DT + dloc];
            const float w10 = Ws1[(k + 0) * DT + dloc];
            const float w11 = Ws1[(k + 1) * DT + dloc];
            const float w12 = Ws1[(k + 2) * DT + dloc];
            const float w13 = Ws1[(k + 3) * DT + dloc];
#pragma unroll
            for (int q = 0; q < 5; q++) {
                if (q < ncnt) {
                    float4 xv = xs4[nrow[q] * (CIN / 4) + k4];
                    acc0[q] = fmaf(xv.x, w00, acc0[q]);
                    acc0[q] = fmaf(xv.y, w01, acc0[q]);
                    acc0[q] = fmaf(xv.z, w02, acc0[q]);
                    acc0[q] = fmaf(xv.w, w03, acc0[q]);
                    acc1[q] = fmaf(xv.x, w10, acc1[q]);
                    acc1[q] = fmaf(xv.y, w11, acc1[q]);
                    acc1[q] = fmaf(xv.z, w12, acc1[q]);
                    acc1[q] = fmaf(xv.w, w13, acc1[q]);
                }
            }
        }

        // Stage g1 = M * h1 for the cross-node aggregation
#pragma unroll
        for (int q = 0; q < 5; q++)
            if (q < ncnt)
                g1s[nrow[q] * DT + dloc] = Msh[nrow[q] * DT + dloc] * acc1[q];
        __syncthreads();

        // out[b,i,d] = Cdiag[i,d]*h0 + sum_j offA[i,j]*g1[j,d] + bias[d]
#pragma unroll
        for (int q = 0; q < 5; q++) {
            if (q < ncnt) {
                const int i = nrow[q];
                float r = fmaf(Cds[i * DT + dloc], acc0[q], bss[dloc]);
#pragma unroll
                for (int j = 0; j < NN; j++)
                    r = fmaf(oAs[i * NN + j], g1s[j * DT + dloc], r);
                out[((size_t)b * NN + i) * COUT + d0 + dloc] = r;
            }
        }
        __syncthreads();  // protect xs/g1s before next b iteration
    }
}

// ---------------------------------------------------------------------------
extern "C" void kernel_launch(void* const* d_in, const int* in_sizes, int n_in,
                              void* d_out, int out_size) {
    const float* x    = (const float*)d_in[0];
    const float* W    = (const float*)d_in[1];
    const float* M    = (const float*)d_in[2];
    const float* adj  = (const float*)d_in[3];
    const float* adj2 = (const float*)d_in[4];
    const float* bias = (const float*)d_in[5];
    float* out = (float*)d_out;

    // smem: 2*16384 + 4352 + 3*1088 + 64 + 289 floats
    const size_t smem_bytes =
        (size_t)(2 * CIN * DT + NN * CIN + 3 * NN * DT + DT + NN * NN) * sizeof(float);
    static bool attr_set = false;
    if (!attr_set) {
        cudaFuncSetAttribute(mgc_kernel,
                             cudaFuncAttributeMaxDynamicSharedMemorySize,
                             (int)smem_bytes);
        attr_set = true;
    }

    prep_kernel<<<1, 256>>>(M, adj, adj2);
    dim3 grid(NTILE, BGRP);
    mgc_kernel<<<grid, 256, smem_bytes>>>(x, W, M, bias, out);
}

// round 3
// speedup vs baseline: 6.7365x; 6.7365x over previous
#include <cuda_runtime.h>
#include <cstdint>
#include <cstddef>

// ---------------------------------------------------------------------------
// Problem constants
// ---------------------------------------------------------------------------
#define BB     8192
#define NNODE  17
#define CIN    256
#define COUT   256
#define NTOT   (BB * NNODE)            // 139264 flat rows
#define TBB    7                       // b's per tile
#define ROWS_T (TBB * NNODE)           // 119 valid rows per tile
#define NTILES ((NTOT + ROWS_T - 1) / ROWS_T)   // 1171
#define SSTR   68                      // padded float stride for epilogue staging

// SMEM byte offsets (dynamic)
#define W_OFF      0                   // 4 mats x 32768 B  (W0hi,W0lo,W1hi,W1lo)
#define X_OFF      131072              // 2 bufs x (hi 16K + lo 16K) = 65536
#define P0_OFF     131072              // epilogue reuse: [128][68] f32 = 34816
#define P1_OFF     165888              // [128][68] f32 = 34816 (ends 200704)
#define MSH_OFF    200704              // [17][64] f32 = 4352
#define CDS_OFF    205056              // [17][64] f32 = 4352
#define BIAS_OFF   209408              // [64] f32 = 256
#define OAS_OFF    209664              // [17][17] f32 = 1156
#define SMEM_BYTES 210944

// ---------------------------------------------------------------------------
// Device globals
// ---------------------------------------------------------------------------
__device__ float d_offA[NNODE * NNODE];   // symmetrized A, diag zeroed
__device__ float d_Cdiag[NNODE * COUT];   // A[i,i] * M[i,d]
// Prepacked W^T: [g 0..3][m 0..3][64 n][256 k] bf16, XOR-swizzled smem image.
// m = w*2 + (0:hi, 1:lo)
__device__ __align__(16) unsigned short d_WT[4 * 4 * 64 * 256];

// ---------------------------------------------------------------------------
// Helpers
// ---------------------------------------------------------------------------
__device__ __forceinline__ uint32_t smem_to_u32(const void* p) {
    uint32_t a;
    asm("{ .reg .u64 t; cvta.to.shared.u64 t, %1; cvt.u32.u64 %0, t; }"
        : "=r"(a) : "l"(p));
    return a;
}
__device__ __forceinline__ void ldsm4(uint32_t* r, uint32_t addr) {
    asm volatile("ldmatrix.sync.aligned.m8n8.x4.shared.b16 {%0,%1,%2,%3}, [%4];"
                 : "=r"(r[0]), "=r"(r[1]), "=r"(r[2]), "=r"(r[3]) : "r"(addr));
}
#define MMA_BF16(ac, A, b0, b1) \
    asm volatile("mma.sync.aligned.m16n8k16.row.col.f32.bf16.bf16.f32 " \
        "{%0,%1,%2,%3}, {%4,%5,%6,%7}, {%8,%9}, {%0,%1,%2,%3};" \
        : "+f"((ac)[0]), "+f"((ac)[1]), "+f"((ac)[2]), "+f"((ac)[3]) \
        : "r"((A)[0]), "r"((A)[1]), "r"((A)[2]), "r"((A)[3]), "r"(b0), "r"(b1))

// ---------------------------------------------------------------------------
// Prep A: symmetrize adj, build offA + Cdiag
// ---------------------------------------------------------------------------
__global__ void prep_small(const float* __restrict__ M,
                           const float* __restrict__ adj,
                           const float* __restrict__ adj2) {
    __shared__ float Asym[NNODE * NNODE];
    int t = threadIdx.x;
    for (int idx = t; idx < NNODE * NNODE; idx += blockDim.x) {
        int i = idx / NNODE, j = idx % NNODE;
        float a = adj[i * NNODE + j] + adj2[i * NNODE + j];
        float b = adj[j * NNODE + i] + adj2[j * NNODE + i];
        Asym[idx] = 0.5f * (a + b);
    }
    __syncthreads();
    for (int idx = t; idx < NNODE * NNODE; idx += blockDim.x) {
        int i = idx / NNODE, j = idx % NNODE;
        d_offA[idx] = (i == j) ? 0.0f : Asym[idx];
    }
    for (int idx = t; idx < NNODE * COUT; idx += blockDim.x) {
        int i = idx >> 8;
        d_Cdiag[idx] = Asym[i * NNODE + i] * M[idx];
    }
}

// ---------------------------------------------------------------------------
// Prep W: W^T -> bf16 hi/lo, [n][k] layout with XOR swizzle (byte ^ (n&7)<<4)
// ---------------------------------------------------------------------------
__global__ void prep_w(const float* __restrict__ W) {
    int idx0 = blockIdx.x * blockDim.x + threadIdx.x;
    for (int idx = idx0; idx < 2 * CIN * COUT; idx += gridDim.x * blockDim.x) {
        int w = idx >> 16;
        int k = (idx >> 8) & 255;
        int n = idx & 255;
        float v = W[w * CIN * COUT + k * COUT + n];
        unsigned short hb, lb;
        asm("cvt.rn.bf16.f32 %0, %1;" : "=h"(hb) : "f"(v));
        float hf = __uint_as_float(((unsigned)hb) << 16);
        asm("cvt.rn.bf16.f32 %0, %1;" : "=h"(lb) : "f"(v - hf));
        int g = n >> 6, nl = n & 63;
        unsigned byte = (unsigned)(nl * 512 + ((k * 2) ^ ((nl & 7) << 4)));
        unsigned base_hi = (unsigned)(g * 4 + w * 2) * 16384u;
        d_WT[base_hi + (byte >> 1)]         = hb;
        d_WT[base_hi + 16384 + (byte >> 1)] = lb;
    }
}

// ---------------------------------------------------------------------------
// Main kernel: HMMA (mma.sync bf16 hi/lo split) dual GEMM + fused aggregation
// grid = 592: g = bid & 3 (64-dout group), sidx = bid >> 2 (tile stream)
// ---------------------------------------------------------------------------
__global__ void __launch_bounds__(256, 1)
mgc_hmma(const float* __restrict__ x,
         const float* __restrict__ M,
         const float* __restrict__ bias,
         float* __restrict__ out) {
    extern __shared__ char smc[];
    const uint32_t smb = smem_to_u32(smc);
    const int t    = threadIdx.x;
    const int wid  = t >> 5;
    const int lid  = t & 31;
    const int g    = blockIdx.x & 3;
    const int sidx = blockIdx.x >> 2;
    const int warp_m = wid & 3;     // 32-row band
    const int warp_n = wid >> 2;    // 32-col band

    // ---- one-time per-CTA setup ----
    {   // W image (128 KB)
        const uint4* wsrc = reinterpret_cast<const uint4*>(d_WT) + (size_t)g * 8192;
        uint4* wdst = reinterpret_cast<uint4*>(smc + W_OFF);
        for (int i = t; i < 8192; i += 256) wdst[i] = wsrc[i];
    }
    float* Msh = (float*)(smc + MSH_OFF);
    float* Cds = (float*)(smc + CDS_OFF);
    float* bss = (float*)(smc + BIAS_OFF);
    float* oAs = (float*)(smc + OAS_OFF);
    for (int idx = t; idx < NNODE * 64; idx += 256) {
        int i = idx >> 6, dl = idx & 63;
        Msh[idx] = M[i * COUT + g * 64 + dl];
        Cds[idx] = d_Cdiag[i * COUT + g * 64 + dl];
    }
    if (t < 64) bss[t] = bias[g * 64 + t];
    for (int idx = t; idx < NNODE * NNODE; idx += 256) oAs[idx] = d_offA[idx];
    // zero-pad x rows 119..127 in both buffers, both planes
    for (int idx = t; idx < 288; idx += 256) {
        int pb = idx / 72, rem = idx % 72;
        uint4* p = reinterpret_cast<uint4*>(
            smc + X_OFF + (pb >> 1) * 32768 + (pb & 1) * 16384 + 119 * 128 + rem * 16);
        *p = make_uint4(0, 0, 0, 0);
    }
    __syncthreads();

    // ---- ldmatrix lane addressing (precomputed) ----
    const uint32_t lxor = (uint32_t)(lid & 7) << 4;   // row&7 == lid&7 everywhere
    // A: groups g0..g3 (lid>>3): rows +{0,8,0,8}, koff {0,0,16,16}
    const int aRow = warp_m * 32 + ((lid >> 3) & 1) * 8 + (lid & 7);
    const uint32_t aKx = (uint32_t)(lid >> 4) * 16;
    uint32_t aBase[2];
#pragma unroll
    for (int mt = 0; mt < 2; mt++) aBase[mt] = smb + X_OFF + (aRow + 16 * mt) * 128;
    // B: groups: rows +{0,0,8,8}, koff {0,16,0,16}
    const int bRow = warp_n * 32 + (lid >> 4) * 8 + (lid & 7);
    const uint32_t bKx = (uint32_t)((lid >> 3) & 1) * 16;
    uint32_t bBase[2];
#pragma unroll
    for (int p = 0; p < 2; p++) bBase[p] = smb + W_OFF + (bRow + 16 * p) * 512;

    const float4* x4 = reinterpret_cast<const float4*>(x);
    float* P0 = (float*)(smc + P0_OFF);
    float* P1 = (float*)(smc + P1_OFF);

    float4 pf[8];

    // prefetch tile sidx, chunk 0
    {
        int tl0 = sidx;
        if (tl0 < NTILES) {
            int prow = tl0 * ROWS_T;
            int pval = min(ROWS_T, NTOT - prow);
#pragma unroll
            for (int j = 0; j < 8; j++) {
                int idx = t + j * 256;
                if (idx < pval * 16)
                    pf[j] = x4[(size_t)(prow + (idx >> 4)) * 64 + (idx & 15)];
            }
        }
    }

    for (int tl = sidx; tl < NTILES; tl += 148) {
        const int row0  = tl * ROWS_T;
        const int valid = min(ROWS_T, NTOT - row0);

        float acc[2][2][4][4];
#pragma unroll
        for (int a = 0; a < 2; a++)
#pragma unroll
            for (int b = 0; b < 2; b++)
#pragma unroll
                for (int c = 0; c < 4; c++)
#pragma unroll
                    for (int d = 0; d < 4; d++) acc[a][b][c][d] = 0.f;

        for (int c = 0; c < 4; c++) {
            const int bi = c & 1;
            // convert + store chunk c (data already in pf)
            char* ahi = smc + X_OFF + bi * 32768;
            char* alo = ahi + 16384;
#pragma unroll
            for (int j = 0; j < 8; j++) {
                int idx = t + j * 256;
                if (idx < valid * 16) {
                    int r = idx >> 4, q = idx & 15;
                    float4 v = pf[j];
                    uint32_t ph0, ph1, pl0, pl1;
                    asm("cvt.rn.bf16x2.f32 %0, %1, %2;" : "=r"(ph0) : "f"(v.y), "f"(v.x));
                    asm("cvt.rn.bf16x2.f32 %0, %1, %2;" : "=r"(ph1) : "f"(v.w), "f"(v.z));
                    float hx = __uint_as_float(ph0 << 16);
                    float hy = __uint_as_float(ph0 & 0xFFFF0000u);
                    float hz = __uint_as_float(ph1 << 16);
                    float hw = __uint_as_float(ph1 & 0xFFFF0000u);
                    asm("cvt.rn.bf16x2.f32 %0, %1, %2;" : "=r"(pl0) : "f"(v.y - hy), "f"(v.x - hx));
                    asm("cvt.rn.bf16x2.f32 %0, %1, %2;" : "=r"(pl1) : "f"(v.w - hw), "f"(v.z - hz));
                    unsigned off = (unsigned)(r * 128 + ((q * 8) ^ ((r & 7) << 4)));
                    *reinterpret_cast<uint2*>(ahi + off) = make_uint2(ph0, ph1);
                    *reinterpret_cast<uint2*>(alo + off) = make_uint2(pl0, pl1);
                }
            }
            // prefetch next chunk / next tile's chunk 0
            if (c < 3) {
#pragma unroll
                for (int j = 0; j < 8; j++) {
                    int idx = t + j * 256;
                    if (idx < valid * 16)
                        pf[j] = x4[(size_t)(row0 + (idx >> 4)) * 64 + (c + 1) * 16 + (idx & 15)];
                }
            } else {
                int tn = tl + 148;
                if (tn < NTILES) {
                    int prow = tn * ROWS_T;
                    int pval = min(ROWS_T, NTOT - prow);
#pragma unroll
                    for (int j = 0; j < 8; j++) {
                        int idx = t + j * 256;
                        if (idx < pval * 16)
                            pf[j] = x4[(size_t)(prow + (idx >> 4)) * 64 + (idx & 15)];
                    }
                }
            }
            __syncthreads();

            // MMA over chunk c: 4 k16 steps
            const uint32_t abuf = (uint32_t)bi * 32768;
#pragma unroll
            for (int s = 0; s < 4; s++) {
                uint32_t Af[2][2][4];   // [plane][mt][4]
                uint32_t Bf[4][2][4];   // [m][pair][4]
                const uint32_t ak = ((uint32_t)(s * 32) + aKx) ^ lxor;
#pragma unroll
                for (int mt = 0; mt < 2; mt++) {
                    ldsm4(Af[0][mt], aBase[mt] + abuf + ak);
                    ldsm4(Af[1][mt], aBase[mt] + abuf + 16384 + ak);
                }
                const uint32_t bk = ((uint32_t)(c * 128 + s * 32) + bKx) ^ lxor;
#pragma unroll
                for (int m = 0; m < 4; m++)
#pragma unroll
                    for (int p = 0; p < 2; p++)
                        ldsm4(Bf[m][p], bBase[p] + (uint32_t)m * 32768 + bk);

#pragma unroll
                for (int w2 = 0; w2 < 2; w2++)
#pragma unroll
                    for (int mt = 0; mt < 2; mt++)
#pragma unroll
                        for (int nt = 0; nt < 4; nt++) {
                            float* ac = acc[w2][mt][nt];
                            const int p = nt >> 1, o = (nt & 1) * 2;
                            MMA_BF16(ac, Af[0][mt], Bf[2 * w2][p][o],     Bf[2 * w2][p][o + 1]);
                            MMA_BF16(ac, Af[0][mt], Bf[2 * w2 + 1][p][o], Bf[2 * w2 + 1][p][o + 1]);
                            MMA_BF16(ac, Af[1][mt], Bf[2 * w2][p][o],     Bf[2 * w2][p][o + 1]);
                        }
            }
        }
        __syncthreads();   // all MMA reads done before P0/P1 overwrite X area

        // ---- epilogue staging: P0 = Cdiag*h0 + bias, P1 = M*h1 ----
        {
            const int colb = warp_n * 32 + (lid & 3) * 2;
            const int rowb = warp_m * 32 + (lid >> 2);
#pragma unroll
            for (int mt = 0; mt < 2; mt++)
#pragma unroll
                for (int rh = 0; rh < 2; rh++) {
                    const int r = rowb + 16 * mt + 8 * rh;
                    const int i = r % NNODE;
#pragma unroll
                    for (int nt = 0; nt < 4; nt++) {
                        const int dl = colb + 8 * nt;
                        float2 mv = *(const float2*)(Msh + i * 64 + dl);
                        float2 cd = *(const float2*)(Cds + i * 64 + dl);
                        float2 bv = *(const float2*)(bss + dl);
                        float h1a = acc[1][mt][nt][2 * rh + 0];
                        float h1b = acc[1][mt][nt][2 * rh + 1];
                        float h0a = acc[0][mt][nt][2 * rh + 0];
                        float h0b = acc[0][mt][nt][2 * rh + 1];
                        *(float2*)(P1 + r * SSTR + dl) = make_float2(mv.x * h1a, mv.y * h1b);
                        *(float2*)(P0 + r * SSTR + dl) =
                            make_float2(fmaf(cd.x, h0a, bv.x), fmaf(cd.y, h0b, bv.y));
                    }
                }
        }
        __syncthreads();

        // ---- aggregation + direct store ----
        {
            const int r2  = t & 127;
            const int dlb = (t >> 7) * 32;
            if (r2 < valid) {
                const int i  = r2 % NNODE;
                const int rb = r2 - i;
                float res[32];
#pragma unroll
                for (int q = 0; q < 8; q++) {
                    float4 p0 = *(const float4*)(P0 + r2 * SSTR + dlb + 4 * q);
                    res[4 * q + 0] = p0.x; res[4 * q + 1] = p0.y;
                    res[4 * q + 2] = p0.z; res[4 * q + 3] = p0.w;
                }
#pragma unroll
                for (int j = 0; j < NNODE; j++) {
                    const float a = oAs[i * NNODE + j];
                    const float* gp = P1 + (rb + j) * SSTR + dlb;
#pragma unroll
                    for (int q = 0; q < 8; q++) {
                        float4 gv = *(const float4*)(gp + 4 * q);
                        res[4 * q + 0] = fmaf(a, gv.x, res[4 * q + 0]);
                        res[4 * q + 1] = fmaf(a, gv.y, res[4 * q + 1]);
                        res[4 * q + 2] = fmaf(a, gv.z, res[4 * q + 2]);
                        res[4 * q + 3] = fmaf(a, gv.w, res[4 * q + 3]);
                    }
                }
                float* op = out + (size_t)(row0 + r2) * COUT + g * 64 + dlb;
#pragma unroll
                for (int q = 0; q < 8; q++)
                    *(float4*)(op + 4 * q) =
                        make_float4(res[4 * q + 0], res[4 * q + 1], res[4 * q + 2], res[4 * q + 3]);
            }
        }
        __syncthreads();   // before next tile's STS into X area
    }
}

// ---------------------------------------------------------------------------
extern "C" void kernel_launch(void* const* d_in, const int* in_sizes, int n_in,
                              void* d_out, int out_size) {
    const float* x    = (const float*)d_in[0];
    const float* W    = (const float*)d_in[1];
    const float* M    = (const float*)d_in[2];
    const float* adj  = (const float*)d_in[3];
    const float* adj2 = (const float*)d_in[4];
    const float* bias = (const float*)d_in[5];
    float* out = (float*)d_out;

    static bool attr_set = false;
    if (!attr_set) {
        cudaFuncSetAttribute(mgc_hmma, cudaFuncAttributeMaxDynamicSharedMemorySize, SMEM_BYTES);
        attr_set = true;
    }

    prep_small<<<1, 256>>>(M, adj, adj2);
    prep_w<<<128, 256>>>(W);
    mgc_hmma<<<592, 256, SMEM_BYTES>>>(x, M, bias, out);
}

// round 4
// speedup vs baseline: 7.4506x; 1.1060x over previous
#include <cuda_runtime.h>
#include <cstdint>
#include <cstddef>

// ---------------------------------------------------------------------------
// Problem constants
// ---------------------------------------------------------------------------
#define BB     8192
#define NNODE  17
#define CIN    256
#define COUT   256
#define NTOT   (BB * NNODE)            // 139264 flat rows
#define TBB    7                       // b's per tile
#define ROWS_T (TBB * NNODE)           // 119 valid rows per tile
#define NTILES ((NTOT + ROWS_T - 1) / ROWS_T)   // 1171
#define SSTR   68                      // padded float stride for staging

// SMEM byte offsets (dynamic)
#define W_OFF      0                   // 4 mats x 32768 B  (W0hi,W0lo,W1hi,W1lo)
#define X_OFF      131072              // 2 bufs x (hi 16K + lo 16K) = 65536
#define P0_OFF     131072              // epilogue reuse: [128][68] f32
#define P1_OFF     165888              // [128][68] f32 (ends 200704)
#define MSH_OFF    200704
#define CDS_OFF    205056
#define BIAS_OFF   209408
#define OAS_OFF    209664
#define SMEM_BYTES 210944

// ---------------------------------------------------------------------------
// Device globals
// ---------------------------------------------------------------------------
__device__ float d_offA[NNODE * NNODE];
__device__ float d_Cdiag[NNODE * COUT];
// Prepacked W^T: [g][m][64 n][256 k] bf16, XOR-swizzled; m = w*2 + (0:hi,1:lo)
__device__ __align__(16) unsigned short d_WT[4 * 4 * 64 * 256];

// ---------------------------------------------------------------------------
// Helpers
// ---------------------------------------------------------------------------
__device__ __forceinline__ uint32_t smem_to_u32(const void* p) {
    uint32_t a;
    asm("{ .reg .u64 t; cvta.to.shared.u64 t, %1; cvt.u32.u64 %0, t; }"
        : "=r"(a) : "l"(p));
    return a;
}
__device__ __forceinline__ void ldsm4(uint32_t* r, uint32_t addr) {
    asm volatile("ldmatrix.sync.aligned.m8n8.x4.shared.b16 {%0,%1,%2,%3}, [%4];"
                 : "=r"(r[0]), "=r"(r[1]), "=r"(r[2]), "=r"(r[3]) : "r"(addr));
}
#define MMA_BF16(ac, A, b0, b1) \
    asm volatile("mma.sync.aligned.m16n8k16.row.col.f32.bf16.bf16.f32 " \
        "{%0,%1,%2,%3}, {%4,%5,%6,%7}, {%8,%9}, {%0,%1,%2,%3};" \
        : "+f"((ac)[0]), "+f"((ac)[1]), "+f"((ac)[2]), "+f"((ac)[3]) \
        : "r"((A)[0]), "r"((A)[1]), "r"((A)[2]), "r"((A)[3]), "r"(b0), "r"(b1))

// One k16 MMA step: load fragments, 3 passes x 16 independent MMAs.
// a0/a1: per-lane A addrs (mt=0/1) incl. buffer + k offsets (hi plane; lo = +16384)
// bb: per-lane B addr (pair 0) incl. k offset; pair1 = +8192, mat stride 32768
__device__ __forceinline__ void mma_step(float (&acc)[2][2][4][4],
                                         uint32_t a0, uint32_t a1, uint32_t bb) {
    uint32_t Af[2][2][4];
    uint32_t Bf[4][2][4];
    ldsm4(Af[0][0], a0);
    ldsm4(Af[0][1], a1);
    ldsm4(Af[1][0], a0 + 16384);
    ldsm4(Af[1][1], a1 + 16384);
#pragma unroll
    for (int m = 0; m < 4; m++)
#pragma unroll
        for (int p = 0; p < 2; p++)
            ldsm4(Bf[m][p], bb + (uint32_t)m * 32768 + (uint32_t)p * 8192);

    // pass 0: xhi * Whi
#pragma unroll
    for (int w2 = 0; w2 < 2; w2++)
#pragma unroll
        for (int mt = 0; mt < 2; mt++)
#pragma unroll
            for (int nt = 0; nt < 4; nt++) {
                const int p = nt >> 1, o = (nt & 1) * 2;
                MMA_BF16(acc[w2][mt][nt], Af[0][mt], Bf[2 * w2][p][o], Bf[2 * w2][p][o + 1]);
            }
    // pass 1: xhi * Wlo
#pragma unroll
    for (int w2 = 0; w2 < 2; w2++)
#pragma unroll
        for (int mt = 0; mt < 2; mt++)
#pragma unroll
            for (int nt = 0; nt < 4; nt++) {
                const int p = nt >> 1, o = (nt & 1) * 2;
                MMA_BF16(acc[w2][mt][nt], Af[0][mt], Bf[2 * w2 + 1][p][o], Bf[2 * w2 + 1][p][o + 1]);
            }
    // pass 2: xlo * Whi
#pragma unroll
    for (int w2 = 0; w2 < 2; w2++)
#pragma unroll
        for (int mt = 0; mt < 2; mt++)
#pragma unroll
            for (int nt = 0; nt < 4; nt++) {
                const int p = nt >> 1, o = (nt & 1) * 2;
                MMA_BF16(acc[w2][mt][nt], Af[1][mt], Bf[2 * w2][p][o], Bf[2 * w2][p][o + 1]);
            }
}

// ---------------------------------------------------------------------------
// Prep (merged): block 0 also builds offA + Cdiag; all blocks pack W
// ---------------------------------------------------------------------------
__global__ void prep_all(const float* __restrict__ W,
                         const float* __restrict__ M,
                         const float* __restrict__ adj,
                         const float* __restrict__ adj2) {
    int t = threadIdx.x;
    if (blockIdx.x == 0) {
        __shared__ float Asym[NNODE * NNODE];
        for (int idx = t; idx < NNODE * NNODE; idx += blockDim.x) {
            int i = idx / NNODE, j = idx % NNODE;
            float a = adj[i * NNODE + j] + adj2[i * NNODE + j];
            float b = adj[j * NNODE + i] + adj2[j * NNODE + i];
            Asym[idx] = 0.5f * (a + b);
        }
        __syncthreads();
        for (int idx = t; idx < NNODE * NNODE; idx += blockDim.x) {
            int i = idx / NNODE, j = idx % NNODE;
            d_offA[idx] = (i == j) ? 0.0f : Asym[idx];
        }
        for (int idx = t; idx < NNODE * COUT; idx += blockDim.x) {
            int i = idx >> 8;
            d_Cdiag[idx] = Asym[i * NNODE + i] * M[idx];
        }
    }
    int idx0 = blockIdx.x * blockDim.x + t;
    for (int idx = idx0; idx < 2 * CIN * COUT; idx += gridDim.x * blockDim.x) {
        int w = idx >> 16;
        int k = (idx >> 8) & 255;
        int n = idx & 255;
        float v = W[w * CIN * COUT + k * COUT + n];
        unsigned short hb, lb;
        asm("cvt.rn.bf16.f32 %0, %1;" : "=h"(hb) : "f"(v));
        float hf = __uint_as_float(((unsigned)hb) << 16);
        asm("cvt.rn.bf16.f32 %0, %1;" : "=h"(lb) : "f"(v - hf));
        int g = n >> 6, nl = n & 63;
        unsigned byte = (unsigned)(nl * 512 + ((k * 2) ^ ((nl & 7) << 4)));
        unsigned base_hi = (unsigned)(g * 4 + w * 2) * 16384u;
        d_WT[base_hi + (byte >> 1)]         = hb;
        d_WT[base_hi + 16384 + (byte >> 1)] = lb;
    }
}

// ---------------------------------------------------------------------------
// Main kernel
// ---------------------------------------------------------------------------
__global__ void __launch_bounds__(256, 1)
mgc_hmma(const float* __restrict__ x,
         const float* __restrict__ M,
         const float* __restrict__ bias,
         float* __restrict__ out) {
    extern __shared__ char smc[];
    const uint32_t smb = smem_to_u32(smc);
    const int t    = threadIdx.x;
    const int wid  = t >> 5;
    const int lid  = t & 31;
    const int g    = blockIdx.x & 3;
    const int sidx = blockIdx.x >> 2;
    const int warp_m = wid & 3;
    const int warp_n = wid >> 2;

    // ---- one-time per-CTA setup ----
    {
        const uint4* wsrc = reinterpret_cast<const uint4*>(d_WT) + (size_t)g * 8192;
        uint4* wdst = reinterpret_cast<uint4*>(smc + W_OFF);
        for (int i = t; i < 8192; i += 256) wdst[i] = wsrc[i];
    }
    float* Msh = (float*)(smc + MSH_OFF);
    float* Cds = (float*)(smc + CDS_OFF);
    float* bss = (float*)(smc + BIAS_OFF);
    float* oAs = (float*)(smc + OAS_OFF);
    for (int idx = t; idx < NNODE * 64; idx += 256) {
        int i = idx >> 6, dl = idx & 63;
        Msh[idx] = M[i * COUT + g * 64 + dl];
        Cds[idx] = d_Cdiag[i * COUT + g * 64 + dl];
    }
    if (t < 64) bss[t] = bias[g * 64 + t];
    for (int idx = t; idx < NNODE * NNODE; idx += 256) oAs[idx] = d_offA[idx];
    // zero-pad rows 119..127 in both buffers, both planes (never overwritten)
    for (int idx = t; idx < 288; idx += 256) {
        int pb = idx / 72, rem = idx % 72;
        uint4* p = reinterpret_cast<uint4*>(
            smc + X_OFF + (pb >> 1) * 32768 + (pb & 1) * 16384 + 119 * 128 + rem * 16);
        *p = make_uint4(0, 0, 0, 0);
    }
    __syncthreads();

    // ---- ldmatrix lane addressing ----
    const uint32_t lxor = (uint32_t)(lid & 7) << 4;
    const int aRow = warp_m * 32 + ((lid >> 3) & 1) * 8 + (lid & 7);
    const uint32_t aKx = (uint32_t)(lid >> 4) * 16;
    uint32_t aBase[2];
#pragma unroll
    for (int mt = 0; mt < 2; mt++) aBase[mt] = smb + X_OFF + (aRow + 16 * mt) * 128;
    const int bRow = warp_n * 32 + (lid >> 4) * 8 + (lid & 7);
    const uint32_t bKx = (uint32_t)((lid >> 3) & 1) * 16;
    const uint32_t bBase0 = smb + W_OFF + bRow * 512;

    const float4* x4 = reinterpret_cast<const float4*>(x);
    float* P0 = (float*)(smc + P0_OFF);
    float* P1 = (float*)(smc + P1_OFF);

    float4 pf[8];

    // prologue: prefetch tile sidx, chunk 0
    if (sidx < NTILES) {
        int prow = sidx * ROWS_T;
        int pval = min(ROWS_T, NTOT - prow);
#pragma unroll
        for (int j = 0; j < 8; j++) {
            int idx = t + j * 256;
            if (idx < pval * 16)
                pf[j] = x4[(size_t)(prow + (idx >> 4)) * 64 + (idx & 15)];
        }
    }

    for (int tl = sidx; tl < NTILES; tl += 148) {
        const int row0  = tl * ROWS_T;
        const int valid = min(ROWS_T, NTOT - row0);

        float acc[2][2][4][4];
#pragma unroll
        for (int a = 0; a < 2; a++)
#pragma unroll
            for (int b = 0; b < 2; b++)
#pragma unroll
                for (int cc = 0; cc < 4; cc++)
#pragma unroll
                    for (int d = 0; d < 4; d++) acc[a][b][cc][d] = 0.f;

        // ---- tile top: STS chunk 0 (pf), prefetch chunk 1, sync ----
        {
            char* ahi = smc + X_OFF;          // chunk 0 -> buf 0
            char* alo = ahi + 16384;
#pragma unroll
            for (int j = 0; j < 8; j++) {
                int idx = t + j * 256;
                if (idx < valid * 16) {
                    int r = idx >> 4, q = idx & 15;
                    float4 v = pf[j];
                    uint32_t ph0, ph1, pl0, pl1;
                    asm("cvt.rn.bf16x2.f32 %0, %1, %2;" : "=r"(ph0) : "f"(v.y), "f"(v.x));
                    asm("cvt.rn.bf16x2.f32 %0, %1, %2;" : "=r"(ph1) : "f"(v.w), "f"(v.z));
                    float hx = __uint_as_float(ph0 << 16);
                    float hy = __uint_as_float(ph0 & 0xFFFF0000u);
                    float hz = __uint_as_float(ph1 << 16);
                    float hw = __uint_as_float(ph1 & 0xFFFF0000u);
                    asm("cvt.rn.bf16x2.f32 %0, %1, %2;" : "=r"(pl0) : "f"(v.y - hy), "f"(v.x - hx));
                    asm("cvt.rn.bf16x2.f32 %0, %1, %2;" : "=r"(pl1) : "f"(v.w - hw), "f"(v.z - hz));
                    unsigned off = (unsigned)(r * 128 + ((q * 8) ^ ((r & 7) << 4)));
                    *reinterpret_cast<uint2*>(ahi + off) = make_uint2(ph0, ph1);
                    *reinterpret_cast<uint2*>(alo + off) = make_uint2(pl0, pl1);
                }
            }
#pragma unroll
            for (int j = 0; j < 8; j++) {
                int idx = t + j * 256;
                if (idx < valid * 16)
                    pf[j] = x4[(size_t)(row0 + (idx >> 4)) * 64 + 16 + (idx & 15)];
            }
        }
        __syncthreads();

        // ---- chunk loop: MMA(c) overlapped with convert/STS(c+1), LDG(c+2) --
#pragma unroll
        for (int c = 0; c < 4; c++) {
            const uint32_t abuf = (uint32_t)(c & 1) * 32768;
            const uint32_t ak0 = aKx ^ lxor;               // s=0
            const uint32_t bk0 = ((uint32_t)(c * 128) + bKx) ^ lxor;

            // MMA step s=0
            mma_step(acc, aBase[0] + abuf + ak0, aBase[1] + abuf + ak0, bBase0 + bk0);

            // convert + STS chunk c+1 into other buffer
            if (c < 3) {
                char* ahi = smc + X_OFF + ((c + 1) & 1) * 32768;
                char* alo = ahi + 16384;
#pragma unroll
                for (int j = 0; j < 8; j++) {
                    int idx = t + j * 256;
                    if (idx < valid * 16) {
                        int r = idx >> 4, q = idx & 15;
                        float4 v = pf[j];
                        uint32_t ph0, ph1, pl0, pl1;
                        asm("cvt.rn.bf16x2.f32 %0, %1, %2;" : "=r"(ph0) : "f"(v.y), "f"(v.x));
                        asm("cvt.rn.bf16x2.f32 %0, %1, %2;" : "=r"(ph1) : "f"(v.w), "f"(v.z));
                        float hx = __uint_as_float(ph0 << 16);
                        float hy = __uint_as_float(ph0 & 0xFFFF0000u);
                        float hz = __uint_as_float(ph1 << 16);
                        float hw = __uint_as_float(ph1 & 0xFFFF0000u);
                        asm("cvt.rn.bf16x2.f32 %0, %1, %2;" : "=r"(pl0) : "f"(v.y - hy), "f"(v.x - hx));
                        asm("cvt.rn.bf16x2.f32 %0, %1, %2;" : "=r"(pl1) : "f"(v.w - hw), "f"(v.z - hz));
                        unsigned off = (unsigned)(r * 128 + ((q * 8) ^ ((r & 7) << 4)));
                        *reinterpret_cast<uint2*>(ahi + off) = make_uint2(ph0, ph1);
                        *reinterpret_cast<uint2*>(alo + off) = make_uint2(pl0, pl1);
                    }
                }
                // prefetch: chunk c+2 of this tile, or next tile's chunk 0
                if (c < 2) {
#pragma unroll
                    for (int j = 0; j < 8; j++) {
                        int idx = t + j * 256;
                        if (idx < valid * 16)
                            pf[j] = x4[(size_t)(row0 + (idx >> 4)) * 64 + (c + 2) * 16 + (idx & 15)];
                    }
                } else {
                    int tn = tl + 148;
                    if (tn < NTILES) {
                        int prow = tn * ROWS_T;
                        int pval = min(ROWS_T, NTOT - prow);
#pragma unroll
                        for (int j = 0; j < 8; j++) {
                            int idx = t + j * 256;
                            if (idx < pval * 16)
                                pf[j] = x4[(size_t)(prow + (idx >> 4)) * 64 + (idx & 15)];
                        }
                    }
                }
            }

            // MMA steps s=1..3
#pragma unroll
            for (int s = 1; s < 4; s++) {
                const uint32_t ak = ((uint32_t)(s * 32) + aKx) ^ lxor;
                const uint32_t bk = ((uint32_t)(c * 128 + s * 32) + bKx) ^ lxor;
                mma_step(acc, aBase[0] + abuf + ak, aBase[1] + abuf + ak, bBase0 + bk);
            }
            __syncthreads();
        }

        // ---- epilogue staging: P0 = Cdiag*h0 + bias, P1 = M*h1 ----
        {
            const int colb = warp_n * 32 + (lid & 3) * 2;
            const int rowb = warp_m * 32 + (lid >> 2);
#pragma unroll
            for (int mt = 0; mt < 2; mt++)
#pragma unroll
                for (int rh = 0; rh < 2; rh++) {
                    const int r = rowb + 16 * mt + 8 * rh;
                    const int i = r % NNODE;
#pragma unroll
                    for (int nt = 0; nt < 4; nt++) {
                        const int dl = colb + 8 * nt;
                        float2 mv = *(const float2*)(Msh + i * 64 + dl);
                        float2 cd = *(const float2*)(Cds + i * 64 + dl);
                        float2 bv = *(const float2*)(bss + dl);
                        float h1a = acc[1][mt][nt][2 * rh + 0];
                        float h1b = acc[1][mt][nt][2 * rh + 1];
                        float h0a = acc[0][mt][nt][2 * rh + 0];
                        float h0b = acc[0][mt][nt][2 * rh + 1];
                        *(float2*)(P1 + r * SSTR + dl) = make_float2(mv.x * h1a, mv.y * h1b);
                        *(float2*)(P0 + r * SSTR + dl) =
                            make_float2(fmaf(cd.x, h0a, bv.x), fmaf(cd.y, h0b, bv.y));
                    }
                }
        }
        __syncthreads();

        // ---- aggregation + direct store ----
        {
            const int r2  = t & 127;
            const int dlb = (t >> 7) * 32;
            if (r2 < valid) {
                const int i  = r2 % NNODE;
                const int rb = r2 - i;
                float res[32];
#pragma unroll
                for (int q = 0; q < 8; q++) {
                    float4 p0 = *(const float4*)(P0 + r2 * SSTR + dlb + 4 * q);
                    res[4 * q + 0] = p0.x; res[4 * q + 1] = p0.y;
                    res[4 * q + 2] = p0.z; res[4 * q + 3] = p0.w;
                }
#pragma unroll
                for (int j = 0; j < NNODE; j++) {
                    const float a = oAs[i * NNODE + j];
                    const float* gp = P1 + (rb + j) * SSTR + dlb;
#pragma unroll
                    for (int q = 0; q < 8; q++) {
                        float4 gv = *(const float4*)(gp + 4 * q);
                        res[4 * q + 0] = fmaf(a, gv.x, res[4 * q + 0]);
                        res[4 * q + 1] = fmaf(a, gv.y, res[4 * q + 1]);
                        res[4 * q + 2] = fmaf(a, gv.z, res[4 * q + 2]);
                        res[4 * q + 3] = fmaf(a, gv.w, res[4 * q + 3]);
                    }
                }
                float* op = out + (size_t)(row0 + r2) * COUT + g * 64 + dlb;
#pragma unroll
                for (int q = 0; q < 8; q++)
                    *(float4*)(op + 4 * q) =
                        make_float4(res[4 * q + 0], res[4 * q + 1], res[4 * q + 2], res[4 * q + 3]);
            }
        }
        __syncthreads();   // before next tile overwrites staging / buffers
    }
}

// ---------------------------------------------------------------------------
extern "C" void kernel_launch(void* const* d_in, const int* in_sizes, int n_in,
                              void* d_out, int out_size) {
    const float* x    = (const float*)d_in[0];
    const float* W    = (const float*)d_in[1];
    const float* M    = (const float*)d_in[2];
    const float* adj  = (const float*)d_in[3];
    const float* adj2 = (const float*)d_in[4];
    const float* bias = (const float*)d_in[5];
    float* out = (float*)d_out;

    static bool attr_set = false;
    if (!attr_set) {
        cudaFuncSetAttribute(mgc_hmma, cudaFuncAttributeMaxDynamicSharedMemorySize, SMEM_BYTES);
        attr_set = true;
    }

    prep_all<<<128, 256>>>(W, M, adj, adj2);
    mgc_hmma<<<592, 256, SMEM_BYTES>>>(x, M, bias, out);
}